// round 2
// baseline (speedup 1.0000x reference)
#include <cuda_runtime.h>

#define FEAT 128
#define NCOL 256
#define MAX_NODES 100000

// Scratch: per-node projected features. P[n][0:128] = x[n]@W1[:128], P[n][128:256] = x[n]@W1[128:]
__device__ float g_P[MAX_NODES * NCOL];
__device__ int g_idx_shift;   // 1 if edge_index is int64, 0 if int32

#define BM 64
#define BN 64
#define BK 16

// ---------------------------------------------------------------------------
// Node GEMM: P[M, 256] = x[M,128] @ Wc[128,256]
// where Wc[k][j] = W1[k][j] (j<128)  and  Wc[k][128+j] = W1[128+k][j]
// ---------------------------------------------------------------------------
__global__ __launch_bounds__(256) void node_gemm(const float* __restrict__ x,
                                                 const float* __restrict__ W1,
                                                 int M)
{
    __shared__ float As[BK][BM];
    __shared__ float Bs[BK][BN];

    const int tid = threadIdx.x;
    const int tx  = tid & 15;    // N direction (0..15)
    const int ty  = tid >> 4;    // M direction (0..15)
    const int mBase = blockIdx.x * BM;
    const int nBase = blockIdx.y * BN;   // 0, 64, 128, 192

    // A-tile load mapping: one float4 of x per thread
    const int a_m  = tid >> 2;          // 0..63
    const int a_k4 = (tid & 3) * 4;     // 0,4,8,12
    // B-tile load mapping: one float4 of W per thread
    const int b_k  = tid >> 4;          // 0..15
    const int b_n4 = (tid & 15) * 4;    // 0..60

    // Which half of W1 this N-tile reads
    const int wRowOff = (nBase < FEAT) ? 0 : FEAT;
    const int wColOff = (nBase < FEAT) ? nBase : (nBase - FEAT);

    float acc[4][4] = {};

    const int gm_a = mBase + a_m;

    for (int kb = 0; kb < FEAT; kb += BK) {
        float4 av = make_float4(0.f, 0.f, 0.f, 0.f);
        if (gm_a < M)
            av = *reinterpret_cast<const float4*>(x + (long long)gm_a * FEAT + kb + a_k4);
        As[a_k4 + 0][a_m] = av.x;
        As[a_k4 + 1][a_m] = av.y;
        As[a_k4 + 2][a_m] = av.z;
        As[a_k4 + 3][a_m] = av.w;

        float4 bv = *reinterpret_cast<const float4*>(
            W1 + (long long)(wRowOff + kb + b_k) * FEAT + wColOff + b_n4);
        *reinterpret_cast<float4*>(&Bs[b_k][b_n4]) = bv;

        __syncthreads();

        #pragma unroll
        for (int k = 0; k < BK; ++k) {
            float4 arv = *reinterpret_cast<const float4*>(&As[k][ty * 4]);
            float4 brv = *reinterpret_cast<const float4*>(&Bs[k][tx * 4]);
            float ar[4] = {arv.x, arv.y, arv.z, arv.w};
            float br[4] = {brv.x, brv.y, brv.z, brv.w};
            #pragma unroll
            for (int i = 0; i < 4; i++)
                #pragma unroll
                for (int j = 0; j < 4; j++)
                    acc[i][j] = fmaf(ar[i], br[j], acc[i][j]);
        }
        __syncthreads();
    }

    #pragma unroll
    for (int i = 0; i < 4; i++) {
        int gm = mBase + ty * 4 + i;
        if (gm < M) {
            float4 o = make_float4(acc[i][0], acc[i][1], acc[i][2], acc[i][3]);
            *reinterpret_cast<float4*>(g_P + (long long)gm * NCOL + nBase + tx * 4) = o;
        }
    }
}

// ---------------------------------------------------------------------------
// Detect edge_index element width. If the buffer is int64 (little-endian,
// values < 2^31), the odd int32 words (high halves) are all zero. If int32,
// those words are random node indices (P(all zero) ~ 1e-20).
// ---------------------------------------------------------------------------
__global__ void detect_idx_width(const int* __restrict__ ei32)
{
    g_idx_shift = (ei32[1] == 0 && ei32[3] == 0 && ei32[5] == 0 && ei32[7] == 0) ? 1 : 0;
}

// ---------------------------------------------------------------------------
// Edge kernel: one warp per edge.
// h = relu(P[r,0:128] + P[c,128:256] + b1);  out = sigmoid(h . W2 + b2)
// ---------------------------------------------------------------------------
__global__ __launch_bounds__(256) void edge_kernel(const int* __restrict__ ei32,
                                                   const float* __restrict__ b1,
                                                   const float* __restrict__ W2,
                                                   const float* __restrict__ b2,
                                                   float* __restrict__ out,
                                                   int E)
{
    const int gw   = (blockIdx.x * blockDim.x + threadIdx.x) >> 5;
    const int lane = threadIdx.x & 31;
    if (gw >= E) return;

    const int shift = g_idx_shift;                 // 0: int32, 1: int64 (read low word)
    const int r = ei32[(long long)gw << shift];
    const int c = ei32[(long long)(E + gw) << shift];

    const float4 a  = *reinterpret_cast<const float4*>(g_P + (long long)r * NCOL + lane * 4);
    const float4 b  = *reinterpret_cast<const float4*>(g_P + (long long)c * NCOL + FEAT + lane * 4);
    const float4 bb = reinterpret_cast<const float4*>(b1)[lane];
    const float4 w  = reinterpret_cast<const float4*>(W2)[lane];

    float h0 = fmaxf(a.x + b.x + bb.x, 0.f);
    float h1 = fmaxf(a.y + b.y + bb.y, 0.f);
    float h2 = fmaxf(a.z + b.z + bb.z, 0.f);
    float h3 = fmaxf(a.w + b.w + bb.w, 0.f);

    float acc = h0 * w.x + h1 * w.y + h2 * w.z + h3 * w.w;

    #pragma unroll
    for (int off = 16; off; off >>= 1)
        acc += __shfl_xor_sync(0xffffffffu, acc, off);

    if (lane == 0) {
        float z = acc + b2[0];
        out[gw] = 1.0f / (1.0f + __expf(-z));
    }
}

// ---------------------------------------------------------------------------
extern "C" void kernel_launch(void* const* d_in, const int* in_sizes, int n_in,
                              void* d_out, int out_size)
{
    const float* x   = (const float*)d_in[0];
    const int*   ei  = (const int*)d_in[1];   // width detected on-device
    const float* W1  = (const float*)d_in[2];
    const float* b1  = (const float*)d_in[3];
    const float* W2  = (const float*)d_in[4];
    const float* b2  = (const float*)d_in[5];
    float* out = (float*)d_out;

    const int M = in_sizes[0] / FEAT;   // 100000 nodes
    const int E = in_sizes[1] / 2;      // 600000 edges (element count is dtype-independent? no —
                                        // int64 reports 1200000 elems? in_sizes counts elements of
                                        // the declared dtype; /2 gives E for [2,E] either way)

    detect_idx_width<<<1, 1>>>(ei);

    dim3 ggrid((M + BM - 1) / BM, NCOL / BN);
    node_gemm<<<ggrid, 256>>>(x, W1, M);

    const int warpsPerBlock = 256 / 32;
    const int blocks = (E + warpsPerBlock - 1) / warpsPerBlock;
    edge_kernel<<<blocks, 256>>>(ei, b1, W2, b2, out, E);
}

// round 4
// speedup vs baseline: 1.5392x; 1.5392x over previous
#include <cuda_runtime.h>
#include <cuda_bf16.h>
#include <cuda_fp16.h>
#include <cstdint>

#define FEAT 128
#define NCOL 256
#define MAX_NODES 100000
#define BM 128
#define STRIDE_B 272              // bytes per smem row (136 bf16): conflict-free ldmatrix

// Scratch: per-node projected features, fp16.
// P[n][0:128] = x[n]@W1[:128], P[n][128:256] = x[n]@W1[128:]
__device__ __half g_Ph[(size_t)MAX_NODES * NCOL];

// smem layout: A_hi, A_lo (128 rows m x 128 k), B_hi, B_lo (128 rows k x 128 n)
#define SA (128 * STRIDE_B)       // 34816 B per tile
#define OFF_AH 0
#define OFF_AL (SA)
#define OFF_BH (2 * SA)
#define OFF_BL (3 * SA)
#define SMEM_TOTAL (4 * SA)       // 139264 B

__device__ __forceinline__ uint32_t smem_u32(const void* p) {
    uint32_t a;
    asm("{ .reg .u64 t; cvta.to.shared.u64 t, %1; cvt.u32.u64 %0, t; }" : "=r"(a) : "l"(p));
    return a;
}

__device__ __forceinline__ void ldm_x4(uint32_t* r, uint32_t addr) {
    asm volatile("ldmatrix.sync.aligned.m8n8.x4.shared.b16 {%0,%1,%2,%3}, [%4];"
                 : "=r"(r[0]), "=r"(r[1]), "=r"(r[2]), "=r"(r[3]) : "r"(addr));
}
__device__ __forceinline__ void ldm_x4_t(uint32_t* r, uint32_t addr) {
    asm volatile("ldmatrix.sync.aligned.m8n8.x4.trans.shared.b16 {%0,%1,%2,%3}, [%4];"
                 : "=r"(r[0]), "=r"(r[1]), "=r"(r[2]), "=r"(r[3]) : "r"(addr));
}
__device__ __forceinline__ void mma_bf16(float* d, const uint32_t* a, const uint32_t* b) {
    asm volatile(
        "mma.sync.aligned.m16n8k16.row.col.f32.bf16.bf16.f32 "
        "{%0,%1,%2,%3}, {%4,%5,%6,%7}, {%8,%9}, {%0,%1,%2,%3};"
        : "+f"(d[0]), "+f"(d[1]), "+f"(d[2]), "+f"(d[3])
        : "r"(a[0]), "r"(a[1]), "r"(a[2]), "r"(a[3]), "r"(b[0]), "r"(b[1]));
}

__device__ __forceinline__ uint32_t pack_bf16(float a, float b) {
    __nv_bfloat162 t = __floats2bfloat162_rn(a, b);
    return *reinterpret_cast<uint32_t*>(&t);
}

// ---------------------------------------------------------------------------
// HMMA node GEMM: P[M,256] = x[M,128] @ Wc[128,256] with bf16 hi/lo split.
// grid = (ceil(M/128), 2). blockIdx.y selects N half: Wc[k][n] for y=0 is
// W1[k][n], for y=1 is W1[128+k][n].
// ---------------------------------------------------------------------------
__global__ void __launch_bounds__(256, 1) node_gemm_hmma(const float* __restrict__ x,
                                                         const float* __restrict__ W1,
                                                         int M)
{
    extern __shared__ char smem[];
    const uint32_t sb = smem_u32(smem);
    const int tid  = threadIdx.x;
    const int wid  = tid >> 5;
    const int lane = tid & 31;
    const int mBase = blockIdx.x * BM;
    const int wRow  = blockIdx.y * FEAT;   // row offset into W1

    // ---- Fill A: x[mBase..mBase+127][0..127] -> bf16 hi/lo, [m][k], coalesced ----
    #pragma unroll 4
    for (int it = tid; it < 128 * 32; it += 256) {
        const int r  = it >> 5;
        const int c4 = (it & 31) << 2;
        float4 v = make_float4(0.f, 0.f, 0.f, 0.f);
        const long long gm = mBase + r;
        if (gm < M) v = *reinterpret_cast<const float4*>(x + gm * FEAT + c4);

        float hx = __bfloat162float(__float2bfloat16_rn(v.x));
        float hy = __bfloat162float(__float2bfloat16_rn(v.y));
        float hz = __bfloat162float(__float2bfloat16_rn(v.z));
        float hw = __bfloat162float(__float2bfloat16_rn(v.w));

        uint2 hi = make_uint2(pack_bf16(v.x, v.y), pack_bf16(v.z, v.w));
        uint2 lo = make_uint2(pack_bf16(v.x - hx, v.y - hy), pack_bf16(v.z - hz, v.w - hw));
        const uint32_t o = r * STRIDE_B + c4 * 2;
        *reinterpret_cast<uint2*>(smem + OFF_AH + o) = hi;
        *reinterpret_cast<uint2*>(smem + OFF_AL + o) = lo;
    }
    // ---- Fill B: W1[wRow+k][n] -> bf16 hi/lo, [k][n], coalesced ----
    #pragma unroll 4
    for (int it = tid; it < 128 * 32; it += 256) {
        const int k  = it >> 5;
        const int c4 = (it & 31) << 2;
        float4 v = *reinterpret_cast<const float4*>(W1 + (long long)(wRow + k) * FEAT + c4);

        float hx = __bfloat162float(__float2bfloat16_rn(v.x));
        float hy = __bfloat162float(__float2bfloat16_rn(v.y));
        float hz = __bfloat162float(__float2bfloat16_rn(v.z));
        float hw = __bfloat162float(__float2bfloat16_rn(v.w));

        uint2 hi = make_uint2(pack_bf16(v.x, v.y), pack_bf16(v.z, v.w));
        uint2 lo = make_uint2(pack_bf16(v.x - hx, v.y - hy), pack_bf16(v.z - hz, v.w - hw));
        const uint32_t o = k * STRIDE_B + c4 * 2;
        *reinterpret_cast<uint2*>(smem + OFF_BH + o) = hi;
        *reinterpret_cast<uint2*>(smem + OFF_BL + o) = lo;
    }
    __syncthreads();

    // ---- Main loop: warp (wm, wn) tile = 32 x 64 ----
    const int wm = (wid & 3) * 32;
    const int wn = (wid >> 2) * 64;

    float acc[2][8][4];
    #pragma unroll
    for (int i = 0; i < 2; i++)
        #pragma unroll
        for (int j = 0; j < 8; j++)
            #pragma unroll
            for (int q = 0; q < 4; q++) acc[i][j][q] = 0.f;

    // per-lane ldmatrix address components
    const int aRowIn  = (lane & 7) + ((lane >> 3) & 1) * 8;   // row within 16
    const int aColSel = (lane >> 4) * 8;                      // k block 0/8
    const int bRowIn  = (lane & 7) + ((lane >> 3) & 1) * 8;   // k within 16
    const int bColSel = (lane >> 4) * 8;                      // n block 0/8

    #pragma unroll
    for (int ks = 0; ks < 8; ++ks) {
        const int k0 = ks * 16;
        uint32_t ah[2][4], al[2][4], bh[8][2], bl[8][2];

        #pragma unroll
        for (int mt = 0; mt < 2; ++mt) {
            const uint32_t ao = (wm + mt * 16 + aRowIn) * STRIDE_B + (k0 + aColSel) * 2;
            ldm_x4(ah[mt], sb + OFF_AH + ao);
            ldm_x4(al[mt], sb + OFF_AL + ao);
        }
        #pragma unroll
        for (int np = 0; np < 4; ++np) {
            const uint32_t bo = (k0 + bRowIn) * STRIDE_B + (wn + np * 16 + bColSel) * 2;
            uint32_t th[4], tl[4];
            ldm_x4_t(th, sb + OFF_BH + bo);
            ldm_x4_t(tl, sb + OFF_BL + bo);
            bh[2*np][0] = th[0]; bh[2*np][1] = th[1];
            bh[2*np+1][0] = th[2]; bh[2*np+1][1] = th[3];
            bl[2*np][0] = tl[0]; bl[2*np][1] = tl[1];
            bl[2*np+1][0] = tl[2]; bl[2*np+1][1] = tl[3];
        }
        #pragma unroll
        for (int mt = 0; mt < 2; ++mt)
            #pragma unroll
            for (int nt = 0; nt < 8; ++nt) {
                mma_bf16(acc[mt][nt], ah[mt], bh[nt]);
                mma_bf16(acc[mt][nt], ah[mt], bl[nt]);
                mma_bf16(acc[mt][nt], al[mt], bh[nt]);
            }
    }

    // ---- Epilogue: write fp16 P ----
    const int nGlob = blockIdx.y * FEAT + wn;
    #pragma unroll
    for (int mt = 0; mt < 2; ++mt) {
        const int row0 = mBase + wm + mt * 16 + (lane >> 2);
        #pragma unroll
        for (int nt = 0; nt < 8; ++nt) {
            const int col = nGlob + nt * 8 + (lane & 3) * 2;
            if (row0 < M) {
                __half2 v = __floats2half2_rn(acc[mt][nt][0], acc[mt][nt][1]);
                *reinterpret_cast<__half2*>(g_Ph + (long long)row0 * NCOL + col) = v;
            }
            if (row0 + 8 < M) {
                __half2 v = __floats2half2_rn(acc[mt][nt][2], acc[mt][nt][3]);
                *reinterpret_cast<__half2*>(g_Ph + (long long)(row0 + 8) * NCOL + col) = v;
            }
        }
    }
}

// ---------------------------------------------------------------------------
// Edge kernel: one warp per edge.
// h = relu(P[r,0:128] + P[c,128:256] + b1);  out = sigmoid(h . W2 + b2)
// idx width (int32 vs int64) detected inline from high words.
// ---------------------------------------------------------------------------
__global__ __launch_bounds__(256) void edge_kernel(const int* __restrict__ ei32,
                                                   const float* __restrict__ b1,
                                                   const float* __restrict__ W2,
                                                   const float* __restrict__ b2,
                                                   float* __restrict__ out,
                                                   int E)
{
    const int gw   = (blockIdx.x * blockDim.x + threadIdx.x) >> 5;
    const int lane = threadIdx.x & 31;
    if (gw >= E) return;

    // int64 little-endian high words of small values are all zero
    const int shift = (ei32[1] | ei32[3] | ei32[5] | ei32[7]) == 0 ? 1 : 0;
    const int r = ei32[(long long)gw << shift];
    const int c = ei32[(long long)(E + gw) << shift];

    const uint2 pa = *reinterpret_cast<const uint2*>(g_Ph + (long long)r * NCOL + lane * 4);
    const uint2 pb = *reinterpret_cast<const uint2*>(g_Ph + (long long)c * NCOL + FEAT + lane * 4);
    const float4 bb = reinterpret_cast<const float4*>(b1)[lane];
    const float4 w  = reinterpret_cast<const float4*>(W2)[lane];

    const __half2 a01 = *reinterpret_cast<const __half2*>(&pa.x);
    const __half2 a23 = *reinterpret_cast<const __half2*>(&pa.y);
    const __half2 b01 = *reinterpret_cast<const __half2*>(&pb.x);
    const __half2 b23 = *reinterpret_cast<const __half2*>(&pb.y);

    float2 af01 = __half22float2(a01), af23 = __half22float2(a23);
    float2 bf01 = __half22float2(b01), bf23 = __half22float2(b23);

    float h0 = fmaxf(af01.x + bf01.x + bb.x, 0.f);
    float h1 = fmaxf(af01.y + bf01.y + bb.y, 0.f);
    float h2 = fmaxf(af23.x + bf23.x + bb.z, 0.f);
    float h3 = fmaxf(af23.y + bf23.y + bb.w, 0.f);

    float acc = h0 * w.x + h1 * w.y + h2 * w.z + h3 * w.w;

    #pragma unroll
    for (int off = 16; off; off >>= 1)
        acc += __shfl_xor_sync(0xffffffffu, acc, off);

    if (lane == 0) {
        float z = acc + b2[0];
        out[gw] = 1.0f / (1.0f + __expf(-z));
    }
}

// ---------------------------------------------------------------------------
extern "C" void kernel_launch(void* const* d_in, const int* in_sizes, int n_in,
                              void* d_out, int out_size)
{
    const float* x   = (const float*)d_in[0];
    const int*   ei  = (const int*)d_in[1];
    const float* W1  = (const float*)d_in[2];
    const float* b1  = (const float*)d_in[3];
    const float* W2  = (const float*)d_in[4];
    const float* b2  = (const float*)d_in[5];
    float* out = (float*)d_out;

    const int M = in_sizes[0] / FEAT;
    const int E = in_sizes[1] / 2;

    static bool attr_set = false;
    if (!attr_set) {
        cudaFuncSetAttribute(node_gemm_hmma, cudaFuncAttributeMaxDynamicSharedMemorySize, SMEM_TOTAL);
        attr_set = true;
    }

    dim3 ggrid((M + BM - 1) / BM, 2);
    node_gemm_hmma<<<ggrid, 256, SMEM_TOTAL>>>(x, W1, M);

    const int warpsPerBlock = 256 / 32;
    const int blocks = (E + warpsPerBlock - 1) / warpsPerBlock;
    edge_kernel<<<blocks, 256>>>(ei, b1, W2, b2, out, E);
}

// round 5
// speedup vs baseline: 2.6881x; 1.7464x over previous
#include <cuda_runtime.h>
#include <cuda_bf16.h>
#include <cuda_fp16.h>
#include <cstdint>

#define FEAT 128
#define NCOL 256
#define MAX_NODES 100000
#define BM 128
#define STRIDE_B 272              // bytes per smem row (136 bf16): conflict-free ldmatrix

// Scratch: per-node projected features, fp16.
// P[n][0:128] = x[n]@W1[:128] + b1,  P[n][128:256] = x[n]@W1[128:]
__device__ __half g_Ph[(size_t)MAX_NODES * NCOL];

// smem: A_hi, A_lo (128 m x 128 k), B_hi (128 k x 128 n)
#define SA (128 * STRIDE_B)       // 34816 B per tile
#define OFF_AH 0
#define OFF_AL (SA)
#define OFF_BH (2 * SA)
#define SMEM_TOTAL (3 * SA)       // 104448 B -> 2 CTAs/SM

__device__ __forceinline__ uint32_t smem_u32(const void* p) {
    uint32_t a;
    asm("{ .reg .u64 t; cvta.to.shared.u64 t, %1; cvt.u32.u64 %0, t; }" : "=r"(a) : "l"(p));
    return a;
}
__device__ __forceinline__ void ldm_x4(uint32_t* r, uint32_t addr) {
    asm volatile("ldmatrix.sync.aligned.m8n8.x4.shared.b16 {%0,%1,%2,%3}, [%4];"
                 : "=r"(r[0]), "=r"(r[1]), "=r"(r[2]), "=r"(r[3]) : "r"(addr));
}
__device__ __forceinline__ void ldm_x4_t(uint32_t* r, uint32_t addr) {
    asm volatile("ldmatrix.sync.aligned.m8n8.x4.trans.shared.b16 {%0,%1,%2,%3}, [%4];"
                 : "=r"(r[0]), "=r"(r[1]), "=r"(r[2]), "=r"(r[3]) : "r"(addr));
}
__device__ __forceinline__ void mma_bf16(float* d, const uint32_t* a, const uint32_t* b) {
    asm volatile(
        "mma.sync.aligned.m16n8k16.row.col.f32.bf16.bf16.f32 "
        "{%0,%1,%2,%3}, {%4,%5,%6,%7}, {%8,%9}, {%0,%1,%2,%3};"
        : "+f"(d[0]), "+f"(d[1]), "+f"(d[2]), "+f"(d[3])
        : "r"(a[0]), "r"(a[1]), "r"(a[2]), "r"(a[3]), "r"(b[0]), "r"(b[1]));
}
__device__ __forceinline__ uint32_t pack_bf16(float a, float b) {
    __nv_bfloat162 t = __floats2bfloat162_rn(a, b);
    return *reinterpret_cast<uint32_t*>(&t);
}

// ---------------------------------------------------------------------------
// HMMA node GEMM: P[M,256] = x[M,128] @ Wc[128,256], A hi/lo split (2 products).
// grid = (ceil(M/128), 2). y selects which half of W1 rows / which P columns.
// b1 folded into P[:,0:128] (y==0).
// ---------------------------------------------------------------------------
__global__ void __launch_bounds__(256, 2) node_gemm_hmma(const float* __restrict__ x,
                                                         const float* __restrict__ W1,
                                                         const float* __restrict__ b1,
                                                         int M)
{
    extern __shared__ char smem[];
    const uint32_t sb = smem_u32(smem);
    const int tid  = threadIdx.x;
    const int wid  = tid >> 5;
    const int lane = tid & 31;
    const int mBase = blockIdx.x * BM;
    const int wRow  = blockIdx.y * FEAT;

    // ---- Fill A: x -> bf16 hi/lo, [m][k] ----
    #pragma unroll 4
    for (int it = tid; it < 128 * 32; it += 256) {
        const int r  = it >> 5;
        const int c4 = (it & 31) << 2;
        float4 v = make_float4(0.f, 0.f, 0.f, 0.f);
        const long long gm = mBase + r;
        if (gm < M) v = *reinterpret_cast<const float4*>(x + gm * FEAT + c4);

        float hx = __bfloat162float(__float2bfloat16_rn(v.x));
        float hy = __bfloat162float(__float2bfloat16_rn(v.y));
        float hz = __bfloat162float(__float2bfloat16_rn(v.z));
        float hw = __bfloat162float(__float2bfloat16_rn(v.w));

        uint2 hi = make_uint2(pack_bf16(v.x, v.y), pack_bf16(v.z, v.w));
        uint2 lo = make_uint2(pack_bf16(v.x - hx, v.y - hy), pack_bf16(v.z - hz, v.w - hw));
        const uint32_t o = r * STRIDE_B + c4 * 2;
        *reinterpret_cast<uint2*>(smem + OFF_AH + o) = hi;
        *reinterpret_cast<uint2*>(smem + OFF_AL + o) = lo;
    }
    // ---- Fill B (hi only): W1[wRow+k][n], [k][n] ----
    #pragma unroll 4
    for (int it = tid; it < 128 * 32; it += 256) {
        const int k  = it >> 5;
        const int c4 = (it & 31) << 2;
        float4 v = *reinterpret_cast<const float4*>(W1 + (long long)(wRow + k) * FEAT + c4);
        uint2 hi = make_uint2(pack_bf16(v.x, v.y), pack_bf16(v.z, v.w));
        *reinterpret_cast<uint2*>(smem + OFF_BH + k * STRIDE_B + c4 * 2) = hi;
    }
    __syncthreads();

    const int wm = (wid & 3) * 32;
    const int wn = (wid >> 2) * 64;

    float acc[2][8][4];
    #pragma unroll
    for (int i = 0; i < 2; i++)
        #pragma unroll
        for (int j = 0; j < 8; j++)
            #pragma unroll
            for (int q = 0; q < 4; q++) acc[i][j][q] = 0.f;

    const int aRowIn  = (lane & 7) + ((lane >> 3) & 1) * 8;
    const int aColSel = (lane >> 4) * 8;
    const int bRowIn  = aRowIn;
    const int bColSel = aColSel;

    #pragma unroll
    for (int ks = 0; ks < 8; ++ks) {
        const int k0 = ks * 16;
        uint32_t ah[2][4], al[2][4], bh[8][2];

        #pragma unroll
        for (int mt = 0; mt < 2; ++mt) {
            const uint32_t ao = (wm + mt * 16 + aRowIn) * STRIDE_B + (k0 + aColSel) * 2;
            ldm_x4(ah[mt], sb + OFF_AH + ao);
            ldm_x4(al[mt], sb + OFF_AL + ao);
        }
        #pragma unroll
        for (int np = 0; np < 4; ++np) {
            const uint32_t bo = (k0 + bRowIn) * STRIDE_B + (wn + np * 16 + bColSel) * 2;
            uint32_t th[4];
            ldm_x4_t(th, sb + OFF_BH + bo);
            bh[2*np][0]   = th[0]; bh[2*np][1]   = th[1];
            bh[2*np+1][0] = th[2]; bh[2*np+1][1] = th[3];
        }
        #pragma unroll
        for (int mt = 0; mt < 2; ++mt)
            #pragma unroll
            for (int nt = 0; nt < 8; ++nt) {
                mma_bf16(acc[mt][nt], ah[mt], bh[nt]);
                mma_bf16(acc[mt][nt], al[mt], bh[nt]);
            }
    }

    // ---- Epilogue: add b1 (first half only), write fp16 P ----
    const bool addB = (blockIdx.y == 0);
    const int nGlob = blockIdx.y * FEAT + wn;
    #pragma unroll
    for (int mt = 0; mt < 2; ++mt) {
        const int row0 = mBase + wm + mt * 16 + (lane >> 2);
        #pragma unroll
        for (int nt = 0; nt < 8; ++nt) {
            const int colLoc = wn + nt * 8 + (lane & 3) * 2;  // 0..127 within half
            const int col = nGlob + nt * 8 + (lane & 3) * 2;
            float bx = 0.f, by = 0.f;
            if (addB) { bx = b1[colLoc]; by = b1[colLoc + 1]; }
            if (row0 < M) {
                __half2 v = __floats2half2_rn(acc[mt][nt][0] + bx, acc[mt][nt][1] + by);
                *reinterpret_cast<__half2*>(g_Ph + (long long)row0 * NCOL + col) = v;
            }
            if (row0 + 8 < M) {
                __half2 v = __floats2half2_rn(acc[mt][nt][2] + bx, acc[mt][nt][3] + by);
                *reinterpret_cast<__half2*>(g_Ph + (long long)(row0 + 8) * NCOL + col) = v;
            }
        }
    }
}

// ---------------------------------------------------------------------------
// Edge kernel v2: 4 lanes per edge, grid-stride over edges.
// Lane sub (0..3) owns features [sub*32, sub*32+32). W2 slice lives in regs.
// h = relu(Pa + Pb) (b1 already folded into Pa); out = sigmoid(h.W2 + b2)
// ---------------------------------------------------------------------------
__global__ __launch_bounds__(256) void edge_kernel(const int* __restrict__ ei32,
                                                   const float* __restrict__ W2,
                                                   const float* __restrict__ b2,
                                                   float* __restrict__ out,
                                                   int E, int nQuads)
{
    const int sub  = threadIdx.x & 3;
    const int quad = (blockIdx.x * blockDim.x + threadIdx.x) >> 2;

    // W2 slice -> 32 floats in registers
    float w[32];
    {
        const float4* w4 = reinterpret_cast<const float4*>(W2 + sub * 32);
        #pragma unroll
        for (int i = 0; i < 8; ++i) {
            float4 v = w4[i];
            w[i*4+0] = v.x; w[i*4+1] = v.y; w[i*4+2] = v.z; w[i*4+3] = v.w;
        }
    }
    const float bias2 = b2[0];
    // int64 little-endian high words of small values are all zero
    const int shift = (ei32[1] | ei32[3] | ei32[5] | ei32[7]) == 0 ? 1 : 0;
    const __half2 z2 = __floats2half2_rn(0.f, 0.f);

    for (int e = quad; e < E; e += nQuads) {
        const int r = ei32[(long long)e << shift];
        const int c = ei32[(long long)(E + e) << shift];

        const uint4* pa = reinterpret_cast<const uint4*>(g_Ph + (long long)r * NCOL + sub * 32);
        const uint4* pb = reinterpret_cast<const uint4*>(g_Ph + (long long)c * NCOL + FEAT + sub * 32);

        float acc = 0.f;
        #pragma unroll
        for (int q = 0; q < 4; ++q) {
            uint4 av = pa[q];
            uint4 bv = pb[q];
            const __half2* ah = reinterpret_cast<const __half2*>(&av);
            const __half2* bh = reinterpret_cast<const __half2*>(&bv);
            #pragma unroll
            for (int j = 0; j < 4; ++j) {
                __half2 s = __hmax2(__hadd2(ah[j], bh[j]), z2);
                float2 f = __half22float2(s);
                acc = fmaf(f.x, w[q*8 + j*2],     acc);
                acc = fmaf(f.y, w[q*8 + j*2 + 1], acc);
            }
        }
        acc += __shfl_xor_sync(0xffffffffu, acc, 1);
        acc += __shfl_xor_sync(0xffffffffu, acc, 2);

        if (sub == 0) {
            float zv = acc + bias2;
            out[e] = 1.0f / (1.0f + __expf(-zv));
        }
    }
}

// ---------------------------------------------------------------------------
extern "C" void kernel_launch(void* const* d_in, const int* in_sizes, int n_in,
                              void* d_out, int out_size)
{
    const float* x   = (const float*)d_in[0];
    const int*   ei  = (const int*)d_in[1];
    const float* W1  = (const float*)d_in[2];
    const float* b1  = (const float*)d_in[3];
    const float* W2  = (const float*)d_in[4];
    const float* b2  = (const float*)d_in[5];
    float* out = (float*)d_out;

    const int M = in_sizes[0] / FEAT;
    const int E = in_sizes[1] / 2;

    static bool attr_set = false;
    if (!attr_set) {
        cudaFuncSetAttribute(node_gemm_hmma, cudaFuncAttributeMaxDynamicSharedMemorySize, SMEM_TOTAL);
        attr_set = true;
    }

    dim3 ggrid((M + BM - 1) / BM, 2);
    node_gemm_hmma<<<ggrid, 256, SMEM_TOTAL>>>(x, W1, b1, M);

    const int blocks = 1184;                       // ~8 SM waves of quads
    const int nQuads = blocks * (256 / 4);
    edge_kernel<<<blocks, 256>>>(ei, W2, b2, out, E, nQuads);
}

// round 6
// speedup vs baseline: 2.9252x; 1.0882x over previous
#include <cuda_runtime.h>
#include <cuda_bf16.h>
#include <cuda_fp16.h>
#include <cstdint>

#define FEAT 128
#define NCOL 256
#define MAX_NODES 100000
#define BM 128
#define STRIDE_B 272              // bytes per smem row (136 bf16): conflict-free ldmatrix

// Scratch: per-node projected features, fp16.
// P[n][0:128] = x[n]@W1[:128] + b1,  P[n][128:256] = x[n]@W1[128:]
__device__ __half g_Ph[(size_t)MAX_NODES * NCOL];

// smem: A_hi, A_lo (128 m x 128 k), B_hi (128 k x 128 n, refilled per half)
#define SA (128 * STRIDE_B)       // 34816 B per tile
#define OFF_AH 0
#define OFF_AL (SA)
#define OFF_BH (2 * SA)
#define SMEM_TOTAL (3 * SA)       // 104448 B -> 2 CTAs/SM

__device__ __forceinline__ uint32_t smem_u32(const void* p) {
    uint32_t a;
    asm("{ .reg .u64 t; cvta.to.shared.u64 t, %1; cvt.u32.u64 %0, t; }" : "=r"(a) : "l"(p));
    return a;
}
__device__ __forceinline__ void ldm_x4(uint32_t* r, uint32_t addr) {
    asm volatile("ldmatrix.sync.aligned.m8n8.x4.shared.b16 {%0,%1,%2,%3}, [%4];"
                 : "=r"(r[0]), "=r"(r[1]), "=r"(r[2]), "=r"(r[3]) : "r"(addr));
}
__device__ __forceinline__ void ldm_x4_t(uint32_t* r, uint32_t addr) {
    asm volatile("ldmatrix.sync.aligned.m8n8.x4.trans.shared.b16 {%0,%1,%2,%3}, [%4];"
                 : "=r"(r[0]), "=r"(r[1]), "=r"(r[2]), "=r"(r[3]) : "r"(addr));
}
__device__ __forceinline__ void mma_bf16(float* d, const uint32_t* a, const uint32_t* b) {
    asm volatile(
        "mma.sync.aligned.m16n8k16.row.col.f32.bf16.bf16.f32 "
        "{%0,%1,%2,%3}, {%4,%5,%6,%7}, {%8,%9}, {%0,%1,%2,%3};"
        : "+f"(d[0]), "+f"(d[1]), "+f"(d[2]), "+f"(d[3])
        : "r"(a[0]), "r"(a[1]), "r"(a[2]), "r"(a[3]), "r"(b[0]), "r"(b[1]));
}
__device__ __forceinline__ uint32_t pack_bf16(float a, float b) {
    __nv_bfloat162 t = __floats2bfloat162_rn(a, b);
    return *reinterpret_cast<uint32_t*>(&t);
}

// ---------------------------------------------------------------------------
// HMMA node GEMM: P[M,256] = x[M,128] @ Wc[128,256], A hi/lo split (2 products).
// One CTA per 128-row tile; loops over both N-halves so x/A-split is done once.
// b1 folded into P[:,0:128].
// ---------------------------------------------------------------------------
__global__ void __launch_bounds__(256, 2) node_gemm_hmma(const float* __restrict__ x,
                                                         const float* __restrict__ W1,
                                                         const float* __restrict__ b1,
                                                         int M)
{
    extern __shared__ char smem[];
    const uint32_t sb = smem_u32(smem);
    const int tid  = threadIdx.x;
    const int wid  = tid >> 5;
    const int lane = tid & 31;
    const int mBase = blockIdx.x * BM;

    // ---- Fill A: x -> bf16 hi/lo, [m][k] (ONCE) ----
    #pragma unroll 4
    for (int it = tid; it < 128 * 32; it += 256) {
        const int r  = it >> 5;
        const int c4 = (it & 31) << 2;
        float4 v = make_float4(0.f, 0.f, 0.f, 0.f);
        const long long gm = mBase + r;
        if (gm < M) v = *reinterpret_cast<const float4*>(x + gm * FEAT + c4);

        float hx = __bfloat162float(__float2bfloat16_rn(v.x));
        float hy = __bfloat162float(__float2bfloat16_rn(v.y));
        float hz = __bfloat162float(__float2bfloat16_rn(v.z));
        float hw = __bfloat162float(__float2bfloat16_rn(v.w));

        uint2 hi = make_uint2(pack_bf16(v.x, v.y), pack_bf16(v.z, v.w));
        uint2 lo = make_uint2(pack_bf16(v.x - hx, v.y - hy), pack_bf16(v.z - hz, v.w - hw));
        const uint32_t o = r * STRIDE_B + c4 * 2;
        *reinterpret_cast<uint2*>(smem + OFF_AH + o) = hi;
        *reinterpret_cast<uint2*>(smem + OFF_AL + o) = lo;
    }

    const int wm = (wid & 3) * 32;
    const int wn = (wid >> 2) * 64;
    const int aRowIn  = (lane & 7) + ((lane >> 3) & 1) * 8;
    const int aColSel = (lane >> 4) * 8;

    for (int h = 0; h < 2; ++h) {
        // ---- Fill B (hi only): W1[h*128+k][n], [k][n] ----
        #pragma unroll 4
        for (int it = tid; it < 128 * 32; it += 256) {
            const int k  = it >> 5;
            const int c4 = (it & 31) << 2;
            float4 v = *reinterpret_cast<const float4*>(W1 + (long long)(h * FEAT + k) * FEAT + c4);
            uint2 hi = make_uint2(pack_bf16(v.x, v.y), pack_bf16(v.z, v.w));
            *reinterpret_cast<uint2*>(smem + OFF_BH + k * STRIDE_B + c4 * 2) = hi;
        }
        __syncthreads();

        float acc[2][8][4];
        #pragma unroll
        for (int i = 0; i < 2; i++)
            #pragma unroll
            for (int j = 0; j < 8; j++)
                #pragma unroll
                for (int q = 0; q < 4; q++) acc[i][j][q] = 0.f;

        #pragma unroll
        for (int ks = 0; ks < 8; ++ks) {
            const int k0 = ks * 16;
            uint32_t ah[2][4], al[2][4], bh[8][2];

            #pragma unroll
            for (int mt = 0; mt < 2; ++mt) {
                const uint32_t ao = (wm + mt * 16 + aRowIn) * STRIDE_B + (k0 + aColSel) * 2;
                ldm_x4(ah[mt], sb + OFF_AH + ao);
                ldm_x4(al[mt], sb + OFF_AL + ao);
            }
            #pragma unroll
            for (int np = 0; np < 4; ++np) {
                const uint32_t bo = (k0 + aRowIn) * STRIDE_B + (wn + np * 16 + aColSel) * 2;
                uint32_t th[4];
                ldm_x4_t(th, sb + OFF_BH + bo);
                bh[2*np][0]   = th[0]; bh[2*np][1]   = th[1];
                bh[2*np+1][0] = th[2]; bh[2*np+1][1] = th[3];
            }
            #pragma unroll
            for (int mt = 0; mt < 2; ++mt)
                #pragma unroll
                for (int nt = 0; nt < 8; ++nt) {
                    mma_bf16(acc[mt][nt], ah[mt], bh[nt]);
                    mma_bf16(acc[mt][nt], al[mt], bh[nt]);
                }
        }

        // ---- Epilogue: add b1 (first half only), write fp16 P ----
        const bool addB = (h == 0);
        #pragma unroll
        for (int mt = 0; mt < 2; ++mt) {
            const int row0 = mBase + wm + mt * 16 + (lane >> 2);
            #pragma unroll
            for (int nt = 0; nt < 8; ++nt) {
                const int colLoc = wn + nt * 8 + (lane & 3) * 2;   // 0..127 within half
                const int col = h * FEAT + colLoc;
                float bx = 0.f, by = 0.f;
                if (addB) { bx = b1[colLoc]; by = b1[colLoc + 1]; }
                if (row0 < M) {
                    __half2 v = __floats2half2_rn(acc[mt][nt][0] + bx, acc[mt][nt][1] + by);
                    *reinterpret_cast<__half2*>(g_Ph + (long long)row0 * NCOL + col) = v;
                }
                if (row0 + 8 < M) {
                    __half2 v = __floats2half2_rn(acc[mt][nt][2] + bx, acc[mt][nt][3] + by);
                    *reinterpret_cast<__half2*>(g_Ph + (long long)(row0 + 8) * NCOL + col) = v;
                }
            }
        }
        __syncthreads();   // B smem reusable for next half
    }
}

// ---------------------------------------------------------------------------
// Edge kernel v3: 8 lanes per edge, grid-stride.
// Lane o (0..7) owns bytes [o*16, o*16+16) of each 128B line (2 lines/side):
// every LDG.128 covers exactly one 128B cache line per edge -> 4 L1 wf/edge.
// h = relu(Pa + Pb) (b1 folded into Pa); out = sigmoid(h.W2 + b2)
// ---------------------------------------------------------------------------
__global__ __launch_bounds__(256) void edge_kernel(const int* __restrict__ ei32,
                                                   const float* __restrict__ W2,
                                                   const float* __restrict__ b2,
                                                   float* __restrict__ out,
                                                   int E, int nOcts)
{
    const int o   = threadIdx.x & 7;
    const int oct = (blockIdx.x * blockDim.x + threadIdx.x) >> 3;

    // W2 slice: halfs handled by this lane are [o*8, o*8+8) and [64+o*8, 64+o*8+8)
    float w[16];
    {
        const float4* w4a = reinterpret_cast<const float4*>(W2 + o * 8);
        const float4* w4b = reinterpret_cast<const float4*>(W2 + 64 + o * 8);
        #pragma unroll
        for (int i = 0; i < 2; ++i) {
            float4 v = w4a[i];
            w[i*4+0] = v.x; w[i*4+1] = v.y; w[i*4+2] = v.z; w[i*4+3] = v.w;
            float4 u = w4b[i];
            w[8+i*4+0] = u.x; w[8+i*4+1] = u.y; w[8+i*4+2] = u.z; w[8+i*4+3] = u.w;
        }
    }
    const float bias2 = b2[0];
    // int64 little-endian high words of small values are all zero
    const int shift = (ei32[1] | ei32[3] | ei32[5] | ei32[7]) == 0 ? 1 : 0;
    const __half2 z2 = __floats2half2_rn(0.f, 0.f);

    for (int e = oct; e < E; e += nOcts) {
        const int r = ei32[(long long)e << shift];
        const int c = ei32[(long long)(E + e) << shift];

        const __half* pa = g_Ph + (long long)r * NCOL;          // halfs 0..127
        const __half* pb = g_Ph + (long long)c * NCOL + FEAT;   // halfs 0..127 of 2nd half

        float acc = 0.f;
        #pragma unroll
        for (int i = 0; i < 2; ++i) {
            // lane o covers halfs [i*64 + o*8, +8)  (byte i*128 + o*16)
            uint4 av = *reinterpret_cast<const uint4*>(pa + i * 64 + o * 8);
            uint4 bv = *reinterpret_cast<const uint4*>(pb + i * 64 + o * 8);
            const __half2* ah = reinterpret_cast<const __half2*>(&av);
            const __half2* bh = reinterpret_cast<const __half2*>(&bv);
            #pragma unroll
            for (int j = 0; j < 4; ++j) {
                __half2 s = __hmax2(__hadd2(ah[j], bh[j]), z2);
                float2 f = __half22float2(s);
                acc = fmaf(f.x, w[i*8 + j*2],     acc);
                acc = fmaf(f.y, w[i*8 + j*2 + 1], acc);
            }
        }
        acc += __shfl_xor_sync(0xffffffffu, acc, 1);
        acc += __shfl_xor_sync(0xffffffffu, acc, 2);
        acc += __shfl_xor_sync(0xffffffffu, acc, 4);

        if (o == 0) {
            float zv = acc + bias2;
            out[e] = 1.0f / (1.0f + __expf(-zv));
        }
    }
}

// ---------------------------------------------------------------------------
extern "C" void kernel_launch(void* const* d_in, const int* in_sizes, int n_in,
                              void* d_out, int out_size)
{
    const float* x   = (const float*)d_in[0];
    const int*   ei  = (const int*)d_in[1];
    const float* W1  = (const float*)d_in[2];
    const float* b1  = (const float*)d_in[3];
    const float* W2  = (const float*)d_in[4];
    const float* b2  = (const float*)d_in[5];
    float* out = (float*)d_out;

    const int M = in_sizes[0] / FEAT;
    const int E = in_sizes[1] / 2;

    static bool attr_set = false;
    if (!attr_set) {
        cudaFuncSetAttribute(node_gemm_hmma, cudaFuncAttributeMaxDynamicSharedMemorySize, SMEM_TOTAL);
        attr_set = true;
    }

    const int nTiles = (M + BM - 1) / BM;
    node_gemm_hmma<<<nTiles, 256, SMEM_TOTAL>>>(x, W1, b1, M);

    const int blocks = 1184;                      // 148 SMs x 8 blocks
    const int nOcts = blocks * (256 / 8);
    edge_kernel<<<blocks, 256>>>(ei, W2, b2, out, E, nOcts);
}

// round 7
// speedup vs baseline: 3.3145x; 1.1331x over previous
#include <cuda_runtime.h>
#include <cuda_bf16.h>
#include <cuda_fp16.h>
#include <cstdint>

#define FEAT 128
#define NCOL 256
#define MAX_NODES 100000
#define BM 128
#define STRIDE_B 272              // bytes per smem row (136 bf16): conflict-free ldmatrix

// Scratch: per-node projected features, fp16 (b1 folded into first half).
__device__ __half g_Ph[(size_t)MAX_NODES * NCOL];
// Pre-converted bf16 weights: [h][k][n], n contiguous
__device__ __nv_bfloat16 g_Wb[2 * FEAT * FEAT];

// smem: A_hi, A_lo (128 m x 128 k), B (128 k x 128 n, refilled per half)
#define SA (128 * STRIDE_B)
#define OFF_AH 0
#define OFF_AL (SA)
#define OFF_BH (2 * SA)
#define SMEM_TOTAL (3 * SA)       // 104448 B -> 2 CTAs/SM

__device__ __forceinline__ uint32_t smem_u32(const void* p) {
    uint32_t a;
    asm("{ .reg .u64 t; cvta.to.shared.u64 t, %1; cvt.u32.u64 %0, t; }" : "=r"(a) : "l"(p));
    return a;
}
__device__ __forceinline__ void ldm_x4(uint32_t* r, uint32_t addr) {
    asm volatile("ldmatrix.sync.aligned.m8n8.x4.shared.b16 {%0,%1,%2,%3}, [%4];"
                 : "=r"(r[0]), "=r"(r[1]), "=r"(r[2]), "=r"(r[3]) : "r"(addr));
}
__device__ __forceinline__ void ldm_x4_t(uint32_t* r, uint32_t addr) {
    asm volatile("ldmatrix.sync.aligned.m8n8.x4.trans.shared.b16 {%0,%1,%2,%3}, [%4];"
                 : "=r"(r[0]), "=r"(r[1]), "=r"(r[2]), "=r"(r[3]) : "r"(addr));
}
__device__ __forceinline__ void mma_bf16(float* d, const uint32_t* a, const uint32_t* b) {
    asm volatile(
        "mma.sync.aligned.m16n8k16.row.col.f32.bf16.bf16.f32 "
        "{%0,%1,%2,%3}, {%4,%5,%6,%7}, {%8,%9}, {%0,%1,%2,%3};"
        : "+f"(d[0]), "+f"(d[1]), "+f"(d[2]), "+f"(d[3])
        : "r"(a[0]), "r"(a[1]), "r"(a[2]), "r"(a[3]), "r"(b[0]), "r"(b[1]));
}
__device__ __forceinline__ uint32_t pack_bf16(float a, float b) {
    __nv_bfloat162 t = __floats2bfloat162_rn(a, b);
    return *reinterpret_cast<uint32_t*>(&t);
}

// ---------------------------------------------------------------------------
// W1 fp32 -> bf16 pre-convert (one tiny launch)
// ---------------------------------------------------------------------------
__global__ void __launch_bounds__(256) conv_w(const float* __restrict__ W1)
{
    const int i4 = (blockIdx.x * blockDim.x + threadIdx.x) * 4;   // elem index
    if (i4 < 2 * FEAT * FEAT) {
        float4 v = *reinterpret_cast<const float4*>(W1 + i4);
        uint2 hi = make_uint2(pack_bf16(v.x, v.y), pack_bf16(v.z, v.w));
        *reinterpret_cast<uint2*>(g_Wb + i4) = hi;
    }
}

// ---------------------------------------------------------------------------
// HMMA node GEMM: P[M,256] = x[M,128] @ Wc[128,256], A hi/lo split (2 products).
// One CTA per 128-row tile; loops over both N-halves (A converted once).
// ---------------------------------------------------------------------------
__global__ void __launch_bounds__(256, 2) node_gemm_hmma(const float* __restrict__ x,
                                                         const float* __restrict__ b1,
                                                         int M)
{
    extern __shared__ char smem[];
    const uint32_t sb = smem_u32(smem);
    const int tid  = threadIdx.x;
    const int wid  = tid >> 5;
    const int lane = tid & 31;
    const int mBase = blockIdx.x * BM;

    // ---- Fill A: x -> bf16 hi/lo, [m][k] (ONCE) ----
    #pragma unroll 4
    for (int it = tid; it < 128 * 32; it += 256) {
        const int r  = it >> 5;
        const int c4 = (it & 31) << 2;
        float4 v = make_float4(0.f, 0.f, 0.f, 0.f);
        const long long gm = mBase + r;
        if (gm < M) v = *reinterpret_cast<const float4*>(x + gm * FEAT + c4);

        float hx = __bfloat162float(__float2bfloat16_rn(v.x));
        float hy = __bfloat162float(__float2bfloat16_rn(v.y));
        float hz = __bfloat162float(__float2bfloat16_rn(v.z));
        float hw = __bfloat162float(__float2bfloat16_rn(v.w));

        uint2 hi = make_uint2(pack_bf16(v.x, v.y), pack_bf16(v.z, v.w));
        uint2 lo = make_uint2(pack_bf16(v.x - hx, v.y - hy), pack_bf16(v.z - hz, v.w - hw));
        const uint32_t o = r * STRIDE_B + c4 * 2;
        *reinterpret_cast<uint2*>(smem + OFF_AH + o) = hi;
        *reinterpret_cast<uint2*>(smem + OFF_AL + o) = lo;
    }

    const int wm = (wid & 3) * 32;
    const int wn = (wid >> 2) * 64;
    const int aRowIn  = (lane & 7) + ((lane >> 3) & 1) * 8;
    const int aColSel = (lane >> 4) * 8;

    for (int h = 0; h < 2; ++h) {
        // ---- Fill B: pure bf16 copy from g_Wb, [k][n] ----
        #pragma unroll 8
        for (int it = tid; it < 128 * 16; it += 256) {
            const int k  = it >> 4;
            const int c8 = (it & 15) << 3;   // 8 bf16 = 16 B
            uint4 v = *reinterpret_cast<const uint4*>(g_Wb + (h * FEAT + k) * FEAT + c8);
            *reinterpret_cast<uint4*>(smem + OFF_BH + k * STRIDE_B + c8 * 2) = v;
        }
        __syncthreads();

        float acc[2][8][4];
        #pragma unroll
        for (int i = 0; i < 2; i++)
            #pragma unroll
            for (int j = 0; j < 8; j++)
                #pragma unroll
                for (int q = 0; q < 4; q++) acc[i][j][q] = 0.f;

        #pragma unroll
        for (int ks = 0; ks < 8; ++ks) {
            const int k0 = ks * 16;
            uint32_t ah[2][4], al[2][4], bh[8][2];

            #pragma unroll
            for (int mt = 0; mt < 2; ++mt) {
                const uint32_t ao = (wm + mt * 16 + aRowIn) * STRIDE_B + (k0 + aColSel) * 2;
                ldm_x4(ah[mt], sb + OFF_AH + ao);
                ldm_x4(al[mt], sb + OFF_AL + ao);
            }
            #pragma unroll
            for (int np = 0; np < 4; ++np) {
                const uint32_t bo = (k0 + aRowIn) * STRIDE_B + (wn + np * 16 + aColSel) * 2;
                uint32_t th[4];
                ldm_x4_t(th, sb + OFF_BH + bo);
                bh[2*np][0]   = th[0]; bh[2*np][1]   = th[1];
                bh[2*np+1][0] = th[2]; bh[2*np+1][1] = th[3];
            }
            #pragma unroll
            for (int mt = 0; mt < 2; ++mt)
                #pragma unroll
                for (int nt = 0; nt < 8; ++nt) {
                    mma_bf16(acc[mt][nt], ah[mt], bh[nt]);
                    mma_bf16(acc[mt][nt], al[mt], bh[nt]);
                }
        }

        // ---- Epilogue: add b1 (first half only), write fp16 P ----
        const bool addB = (h == 0);
        #pragma unroll
        for (int mt = 0; mt < 2; ++mt) {
            const int row0 = mBase + wm + mt * 16 + (lane >> 2);
            #pragma unroll
            for (int nt = 0; nt < 8; ++nt) {
                const int colLoc = wn + nt * 8 + (lane & 3) * 2;
                const int col = h * FEAT + colLoc;
                float bx = 0.f, by = 0.f;
                if (addB) { bx = b1[colLoc]; by = b1[colLoc + 1]; }
                if (row0 < M) {
                    __half2 v = __floats2half2_rn(acc[mt][nt][0] + bx, acc[mt][nt][1] + by);
                    *reinterpret_cast<__half2*>(g_Ph + (long long)row0 * NCOL + col) = v;
                }
                if (row0 + 8 < M) {
                    __half2 v = __floats2half2_rn(acc[mt][nt][2] + bx, acc[mt][nt][3] + by);
                    *reinterpret_cast<__half2*>(g_Ph + (long long)(row0 + 8) * NCOL + col) = v;
                }
            }
        }
        __syncthreads();
    }
}

// ---------------------------------------------------------------------------
// Edge kernel v4: 8 lanes per edge, TWO edges per iteration (MLP=8 LDG.128).
// Lane o owns bytes [o*16,+16) of each 128B line -> 1 L1 wavefront per line.
// ---------------------------------------------------------------------------
__global__ __launch_bounds__(256) void edge_kernel(const int* __restrict__ ei32,
                                                   const float* __restrict__ W2,
                                                   const float* __restrict__ b2,
                                                   float* __restrict__ out,
                                                   int E, int nOcts)
{
    const int o   = threadIdx.x & 7;
    const int oct = (blockIdx.x * blockDim.x + threadIdx.x) >> 3;

    // W2 slice for this lane: [o*8,+8) and [64+o*8,+8)
    float w[16];
    {
        const float4* w4a = reinterpret_cast<const float4*>(W2 + o * 8);
        const float4* w4b = reinterpret_cast<const float4*>(W2 + 64 + o * 8);
        #pragma unroll
        for (int i = 0; i < 2; ++i) {
            float4 v = w4a[i];
            w[i*4+0] = v.x; w[i*4+1] = v.y; w[i*4+2] = v.z; w[i*4+3] = v.w;
            float4 u = w4b[i];
            w[8+i*4+0] = u.x; w[8+i*4+1] = u.y; w[8+i*4+2] = u.z; w[8+i*4+3] = u.w;
        }
    }
    const float bias2 = b2[0];
    const int shift = (ei32[1] | ei32[3] | ei32[5] | ei32[7]) == 0 ? 1 : 0;
    const __half2 z2 = __floats2half2_rn(0.f, 0.f);

    // two consecutive edges per oct per iteration (E is even for this problem;
    // guard e1 anyway)
    for (int e0 = oct * 2; e0 < E; e0 += 2 * nOcts) {
        const int e1 = e0 + 1;
        const bool has1 = (e1 < E);

        const int r0 = ei32[(long long)e0 << shift];
        const int c0 = ei32[(long long)(E + e0) << shift];
        const int r1 = has1 ? ei32[(long long)e1 << shift] : r0;
        const int c1 = has1 ? ei32[(long long)(E + e1) << shift] : c0;

        const __half* pa0 = g_Ph + (long long)r0 * NCOL;
        const __half* pb0 = g_Ph + (long long)c0 * NCOL + FEAT;
        const __half* pa1 = g_Ph + (long long)r1 * NCOL;
        const __half* pb1 = g_Ph + (long long)c1 * NCOL + FEAT;

        // issue all 8 independent 16B loads
        uint4 av0[2], bv0[2], av1[2], bv1[2];
        #pragma unroll
        for (int i = 0; i < 2; ++i) {
            av0[i] = *reinterpret_cast<const uint4*>(pa0 + i * 64 + o * 8);
            bv0[i] = *reinterpret_cast<const uint4*>(pb0 + i * 64 + o * 8);
            av1[i] = *reinterpret_cast<const uint4*>(pa1 + i * 64 + o * 8);
            bv1[i] = *reinterpret_cast<const uint4*>(pb1 + i * 64 + o * 8);
        }

        float acc0 = 0.f, acc1 = 0.f;
        #pragma unroll
        for (int i = 0; i < 2; ++i) {
            const __half2* ah0 = reinterpret_cast<const __half2*>(&av0[i]);
            const __half2* bh0 = reinterpret_cast<const __half2*>(&bv0[i]);
            const __half2* ah1 = reinterpret_cast<const __half2*>(&av1[i]);
            const __half2* bh1 = reinterpret_cast<const __half2*>(&bv1[i]);
            #pragma unroll
            for (int j = 0; j < 4; ++j) {
                __half2 s0 = __hmax2(__hadd2(ah0[j], bh0[j]), z2);
                __half2 s1 = __hmax2(__hadd2(ah1[j], bh1[j]), z2);
                float2 f0 = __half22float2(s0);
                float2 f1 = __half22float2(s1);
                acc0 = fmaf(f0.x, w[i*8 + j*2],     acc0);
                acc0 = fmaf(f0.y, w[i*8 + j*2 + 1], acc0);
                acc1 = fmaf(f1.x, w[i*8 + j*2],     acc1);
                acc1 = fmaf(f1.y, w[i*8 + j*2 + 1], acc1);
            }
        }
        acc0 += __shfl_xor_sync(0xffffffffu, acc0, 1);
        acc1 += __shfl_xor_sync(0xffffffffu, acc1, 1);
        acc0 += __shfl_xor_sync(0xffffffffu, acc0, 2);
        acc1 += __shfl_xor_sync(0xffffffffu, acc1, 2);
        acc0 += __shfl_xor_sync(0xffffffffu, acc0, 4);
        acc1 += __shfl_xor_sync(0xffffffffu, acc1, 4);

        if (o == 0) {
            out[e0] = 1.0f / (1.0f + __expf(-(acc0 + bias2)));
            if (has1) out[e1] = 1.0f / (1.0f + __expf(-(acc1 + bias2)));
        }
    }
}

// ---------------------------------------------------------------------------
extern "C" void kernel_launch(void* const* d_in, const int* in_sizes, int n_in,
                              void* d_out, int out_size)
{
    const float* x   = (const float*)d_in[0];
    const int*   ei  = (const int*)d_in[1];
    const float* W1  = (const float*)d_in[2];
    const float* b1  = (const float*)d_in[3];
    const float* W2  = (const float*)d_in[4];
    const float* b2  = (const float*)d_in[5];
    float* out = (float*)d_out;

    const int M = in_sizes[0] / FEAT;
    const int E = in_sizes[1] / 2;

    static bool attr_set = false;
    if (!attr_set) {
        cudaFuncSetAttribute(node_gemm_hmma, cudaFuncAttributeMaxDynamicSharedMemorySize, SMEM_TOTAL);
        attr_set = true;
    }

    conv_w<<<(2 * FEAT * FEAT / 4 + 255) / 256, 256>>>(W1);

    const int nTiles = (M + BM - 1) / BM;
    node_gemm_hmma<<<nTiles, 256, SMEM_TOTAL>>>(x, b1, M);

    const int blocks = 1184;
    const int nOcts = blocks * (256 / 8);
    edge_kernel<<<blocks, 256>>>(ei, W2, b2, out, E, nOcts);
}